// round 5
// baseline (speedup 1.0000x reference)
#include <cuda_runtime.h>
#include <math.h>

#define NN 2048
#define DD 256

// ---------------- scratch (device globals; no allocation) ----------------
__device__ float g_msg0[NN * DD];
__device__ float g_msg1[NN * DD];
__device__ float g_e0[NN * NN];
__device__ float g_e1[NN * NN];
__device__ float g_agg[NN * 512];       // [agg0 | agg1]
__device__ float g_gi[NN * 768];
__device__ float g_gh[NN * 768];
__device__ float g_ac0[NN * 4];
__device__ float g_an0[NN * 4];
__device__ float g_ac1[NN * 4];
__device__ float g_an1[NN * 4];

// ---------------- tiny projections: a_cur/a_nb for both edge types ----------------
__global__ void acoef_kernel(const float* __restrict__ x,
                             const float* __restrict__ Wa0, const float* __restrict__ Wa1,
                             float* __restrict__ ac0, float* __restrict__ an0,
                             float* __restrict__ ac1, float* __restrict__ an1) {
    __shared__ float xs[256];
    int i = blockIdx.x, tid = threadIdx.x;
    xs[tid] = x[i * 256 + tid];
    __syncthreads();
    int lane = tid & 31, wid = tid >> 5;
    #pragma unroll
    for (int oo = 0; oo < 2; oo++) {
        int o = wid + oo * 8;          // 0..15
        int t = o >> 3, rem = o & 7;
        int half = rem >> 2, h = rem & 3;
        const float* Wa = t ? Wa1 : Wa0;
        const float* row = Wa + h * 512 + half * 256;
        float s = 0.f;
        #pragma unroll
        for (int k = lane; k < 256; k += 32) s += xs[k] * row[k];
        #pragma unroll
        for (int off = 16; off > 0; off >>= 1) s += __shfl_down_sync(0xffffffffu, s, off);
        if (lane == 0) {
            float* dst = half ? (t ? an1 : an0) : (t ? ac1 : ac0);
            dst[i * 4 + h] = s;
        }
    }
}

// ---------------- generic SGEMM: C[M,Nc] = A[M,K] @ B[Nc,K]^T + bias ----------------
__global__ void sgemm_bias(const float* __restrict__ A, const float* __restrict__ B,
                           const float* __restrict__ bias, float* __restrict__ C,
                           int M, int Nc, int K) {
    __shared__ float As[16][64];
    __shared__ float Bs[16][64];
    int tid = threadIdx.x;
    int tx = tid & 15, ty = tid >> 4;
    int m0 = blockIdx.y * 64, n0 = blockIdx.x * 64;
    float acc[4][4] = {};
    for (int kk = 0; kk < K; kk += 16) {
        #pragma unroll
        for (int i = 0; i < 4; i++) {
            int e = i * 256 + tid;
            int r = e >> 4, c = e & 15;
            As[c][r] = A[(m0 + r) * K + kk + c];
            Bs[c][r] = B[(n0 + r) * K + kk + c];
        }
        __syncthreads();
        #pragma unroll
        for (int k = 0; k < 16; k++) {
            float4 a4 = *(const float4*)&As[k][ty * 4];
            float4 b4 = *(const float4*)&Bs[k][tx * 4];
            float av[4] = {a4.x, a4.y, a4.z, a4.w};
            float bv[4] = {b4.x, b4.y, b4.z, b4.w};
            #pragma unroll
            for (int r = 0; r < 4; r++)
                #pragma unroll
                for (int c = 0; c < 4; c++) acc[r][c] += av[r] * bv[c];
        }
        __syncthreads();
    }
    #pragma unroll
    for (int r = 0; r < 4; r++) {
        int m = m0 + ty * 4 + r;
        #pragma unroll
        for (int c = 0; c < 4; c++) {
            int n = n0 + tx * 4 + c;
            C[m * Nc + n] = acc[r][c] + bias[n];
        }
    }
}

// ---------------- fused transpose + mask: e[i,j] = adj[j,i]!=0 ? w[j,i] : -1 ----------------
__global__ void transpose_mask(const float* __restrict__ adj, const float* __restrict__ w,
                               float* __restrict__ e) {
    __shared__ float tile[32][33];
    int j0 = blockIdx.y * 32, i0 = blockIdx.x * 32;
    int tx = threadIdx.x, ty = threadIdx.y;      // 32 x 8
    #pragma unroll
    for (int r = 0; r < 4; r++) {
        int j = j0 + ty + r * 8;
        int idx = j * NN + i0 + tx;
        float a = adj[idx];
        tile[ty + r * 8][tx] = (a != 0.f) ? w[idx] : -1.0f;
    }
    __syncthreads();
    #pragma unroll
    for (int r = 0; r < 4; r++) {
        int i = i0 + ty + r * 8;
        e[i * NN + j0 + tx] = tile[tx][ty + r * 8];
    }
}

// ---------------- sparse softmax attention + aggregate, one block per target node ----------------
__global__ void attn_agg(const float* __restrict__ eT, const float* __restrict__ msg,
                         const float* __restrict__ acur, const float* __restrict__ anb,
                         const float* __restrict__ ba, float* __restrict__ aggout) {
    __shared__ int   jl[512];
    __shared__ float wl[512];
    __shared__ float sv[512 * 4];
    __shared__ float red[256 * 4];
    __shared__ int   warp_off[8];
    __shared__ int   sbase;
    __shared__ float hmax[4], hsum[4];

    int i = blockIdx.x;
    int tid = threadIdx.x;
    int lane = tid & 31, wid = tid >> 5;

    if (tid == 0) sbase = 0;
    for (int k = tid; k < 2048; k += 256) sv[k] = -INFINITY;
    __syncthreads();

    // deterministic edge compaction (fixed (q, j) order -> fixed fp sum order)
    for (int q = 0; q < 8; q++) {
        int j = q * 256 + tid;
        float v = eT[i * NN + j];
        bool f = (v >= 0.f);
        unsigned m = __ballot_sync(0xffffffffu, f);
        int pre = __popc(m & ((1u << lane) - 1u));
        if (lane == 0) warp_off[wid] = __popc(m);
        __syncthreads();
        if (tid == 0) {
            int s = sbase;
            for (int w2 = 0; w2 < 8; w2++) { int c = warp_off[w2]; warp_off[w2] = s; s += c; }
            sbase = s;
        }
        __syncthreads();
        if (f) {
            int pos = warp_off[wid] + pre;
            if (pos < 512) { jl[pos] = j; wl[pos] = v; }
        }
        __syncthreads();
    }
    int E = sbase;
    if (E == 0) {           // isolated node: softmax*mask == 0
        aggout[i * 512 + tid] = 0.f;
        return;
    }
    if (E > 512) E = 512;

    float ac[4], bah[4];
    #pragma unroll
    for (int h = 0; h < 4; h++) { ac[h] = acur[i * 4 + h]; bah[h] = ba[h]; }

    // per-edge, per-head scaled leaky-relu scores
    for (int e = tid; e < E; e += 256) {
        int j = jl[e]; float w = wl[e];
        #pragma unroll
        for (int h = 0; h < 4; h++) {
            float v = anb[j * 4 + h] + ac[h] + bah[h];
            v = v > 0.f ? v : 0.2f * v;
            sv[e * 4 + h] = v * w;
        }
    }
    __syncthreads();

    // per-head max
    #pragma unroll
    for (int h = 0; h < 4; h++) red[tid * 4 + h] = fmaxf(sv[tid * 4 + h], sv[(tid + 256) * 4 + h]);
    __syncthreads();
    for (int off = 128; off > 0; off >>= 1) {
        if (tid < off)
            #pragma unroll
            for (int h = 0; h < 4; h++) red[tid * 4 + h] = fmaxf(red[tid * 4 + h], red[(tid + off) * 4 + h]);
        __syncthreads();
    }
    if (tid < 4) hmax[tid] = red[tid];
    __syncthreads();

    // exp (padding entries are -inf -> 0)
    for (int e = tid; e < 512; e += 256) {
        #pragma unroll
        for (int h = 0; h < 4; h++) sv[e * 4 + h] = expf(sv[e * 4 + h] - hmax[h]);
    }
    __syncthreads();

    // per-head sum
    #pragma unroll
    for (int h = 0; h < 4; h++) red[tid * 4 + h] = sv[tid * 4 + h] + sv[(tid + 256) * 4 + h];
    __syncthreads();
    for (int off = 128; off > 0; off >>= 1) {
        if (tid < off)
            #pragma unroll
            for (int h = 0; h < 4; h++) red[tid * 4 + h] += red[(tid + off) * 4 + h];
        __syncthreads();
    }
    if (tid < 4) hsum[tid] = red[tid];
    __syncthreads();

    for (int e = tid; e < E; e += 256) {
        #pragma unroll
        for (int h = 0; h < 4; h++) sv[e * 4 + h] *= (1.f / hsum[h]);
    }
    __syncthreads();

    // weighted aggregate: thread d owns output dim d (head = d/64); coalesced msg rows
    int d = tid, h = d >> 6;
    float acc = 0.f;
    for (int e = 0; e < E; e++) acc += sv[e * 4 + h] * msg[jl[e] * 256 + d];
    aggout[i * 512 + d] = acc;
}

// ---------------- GRU gates + LayerNorm ----------------
__global__ void gru_ln(const float* __restrict__ gi_, const float* __restrict__ gh_,
                       const float* __restrict__ x, const float* __restrict__ g,
                       const float* __restrict__ b, float* __restrict__ out) {
    int i = blockIdx.x, d = threadIdx.x;
    const float* gi = gi_ + i * 768;
    const float* gh = gh_ + i * 768;
    float r = 1.f / (1.f + expf(-(gi[d] + gh[d])));
    float z = 1.f / (1.f + expf(-(gi[256 + d] + gh[256 + d])));
    float n = tanhf(gi[512 + d] + r * gh[512 + d]);
    float hv = (1.f - z) * n + z * x[i * 256 + d];

    __shared__ float ssum[8], ssq[8];
    __shared__ float mu_s, rs_s;
    float s = hv, q = hv * hv;
    #pragma unroll
    for (int off = 16; off > 0; off >>= 1) {
        s += __shfl_down_sync(0xffffffffu, s, off);
        q += __shfl_down_sync(0xffffffffu, q, off);
    }
    int lane = d & 31, wid = d >> 5;
    if (lane == 0) { ssum[wid] = s; ssq[wid] = q; }
    __syncthreads();
    if (d == 0) {
        float S = 0.f, Q = 0.f;
        for (int w2 = 0; w2 < 8; w2++) { S += ssum[w2]; Q += ssq[w2]; }
        float mu = S / 256.f;
        float var = Q / 256.f - mu * mu;
        mu_s = mu;
        rs_s = rsqrtf(var + 1e-5f);
    }
    __syncthreads();
    out[i * 256 + d] = (hv - mu_s) * rs_s * g[d] + b[d];
}

// ---------------- host orchestration ----------------
extern "C" void kernel_launch(void* const* d_in, const int* in_sizes, int n_in,
                              void* d_out, int out_size) {
    const float* x    = (const float*)d_in[0];
    const float* adj0 = (const float*)d_in[1];
    const float* adj1 = (const float*)d_in[2];
    const float* w0   = (const float*)d_in[3];
    const float* w1   = (const float*)d_in[4];
    const float* Wm0  = (const float*)d_in[5];
    const float* bm0  = (const float*)d_in[6];
    const float* Wa0  = (const float*)d_in[7];
    const float* ba0  = (const float*)d_in[8];
    const float* Wm1  = (const float*)d_in[9];
    const float* bm1  = (const float*)d_in[10];
    const float* Wa1  = (const float*)d_in[11];
    const float* ba1  = (const float*)d_in[12];
    const float* wih  = (const float*)d_in[13];
    const float* whh  = (const float*)d_in[14];
    const float* bih  = (const float*)d_in[15];
    const float* bhh  = (const float*)d_in[16];
    const float* lng  = (const float*)d_in[17];
    const float* lnb  = (const float*)d_in[18];
    float* out = (float*)d_out;

    float *msg0, *msg1, *e0, *e1, *agg, *gi, *gh, *ac0, *an0, *ac1, *an1;
    cudaGetSymbolAddress((void**)&msg0, g_msg0);
    cudaGetSymbolAddress((void**)&msg1, g_msg1);
    cudaGetSymbolAddress((void**)&e0,   g_e0);
    cudaGetSymbolAddress((void**)&e1,   g_e1);
    cudaGetSymbolAddress((void**)&agg,  g_agg);
    cudaGetSymbolAddress((void**)&gi,   g_gi);
    cudaGetSymbolAddress((void**)&gh,   g_gh);
    cudaGetSymbolAddress((void**)&ac0,  g_ac0);
    cudaGetSymbolAddress((void**)&an0,  g_an0);
    cudaGetSymbolAddress((void**)&ac1,  g_ac1);
    cudaGetSymbolAddress((void**)&an1,  g_an1);

    acoef_kernel<<<NN, 256>>>(x, Wa0, Wa1, ac0, an0, ac1, an1);

    sgemm_bias<<<dim3(4, 32), 256>>>(x, Wm0, bm0, msg0, NN, 256, 256);
    sgemm_bias<<<dim3(4, 32), 256>>>(x, Wm1, bm1, msg1, NN, 256, 256);

    transpose_mask<<<dim3(64, 64), dim3(32, 8)>>>(adj0, w0, e0);
    transpose_mask<<<dim3(64, 64), dim3(32, 8)>>>(adj1, w1, e1);

    attn_agg<<<NN, 256>>>(e0, msg0, ac0, an0, ba0, agg);        // cols [0,256)
    attn_agg<<<NN, 256>>>(e1, msg1, ac1, an1, ba1, agg + 256);  // cols [256,512)

    sgemm_bias<<<dim3(12, 32), 256>>>(agg, wih, bih, gi, NN, 768, 512);
    sgemm_bias<<<dim3(12, 32), 256>>>(x,   whh, bhh, gh, NN, 768, 256);

    gru_ln<<<NN, 256>>>(gi, gh, x, lng, lnb, out);
}

// round 6
// speedup vs baseline: 1.6411x; 1.6411x over previous
#include <cuda_runtime.h>
#include <cuda_bf16.h>
#include <math.h>

#define NN 2048
#define DD 256

// ---------------- scratch (device globals; no allocation) ----------------
__device__ float g_msg0[NN * DD];
__device__ float g_msg1[NN * DD];
__device__ float g_e0[NN * NN];
__device__ float g_e1[NN * NN];
__device__ float g_agg[NN * 512];       // [agg0 | agg1]
__device__ float g_gi[NN * 768];
__device__ float g_gh[NN * 768];
__device__ float g_ac0[NN * 4];
__device__ float g_an0[NN * 4];
__device__ float g_ac1[NN * 4];
__device__ float g_an1[NN * 4];

// bf16 split operands
__device__ __nv_bfloat16 g_xhi[NN * 256],  g_xlo[NN * 256];
__device__ __nv_bfloat16 g_ahi[NN * 512],  g_alo[NN * 512];      // agg split
__device__ __nv_bfloat16 g_wm0hi[256 * 256], g_wm0lo[256 * 256];
__device__ __nv_bfloat16 g_wm1hi[256 * 256], g_wm1lo[256 * 256];
__device__ __nv_bfloat16 g_wihhi[768 * 512], g_wihlo[768 * 512];
__device__ __nv_bfloat16 g_whhhi[768 * 256], g_whhlo[768 * 256];

// ---------------- split fp32 -> (hi, lo) bf16, 4-wide ----------------
__global__ void split_bf16(const float* __restrict__ src,
                           __nv_bfloat16* __restrict__ hi,
                           __nv_bfloat16* __restrict__ lo, int n4) {
    int i = blockIdx.x * 256 + threadIdx.x;
    if (i >= n4) return;
    float4 v = ((const float4*)src)[i];
    float vv[4] = {v.x, v.y, v.z, v.w};
    __nv_bfloat16 h[4], l[4];
    #pragma unroll
    for (int k = 0; k < 4; k++) {
        h[k] = __float2bfloat16(vv[k]);
        l[k] = __float2bfloat16(vv[k] - __bfloat162float(h[k]));
    }
    *(uint2*)&hi[i * 4] = *(uint2*)h;
    *(uint2*)&lo[i * 4] = *(uint2*)l;
}

// ---------------- mma helper ----------------
__device__ __forceinline__ void mma16816(float* c, const unsigned* a, const unsigned* b) {
    asm volatile(
        "mma.sync.aligned.m16n8k16.row.col.f32.bf16.bf16.f32 "
        "{%0,%1,%2,%3},{%4,%5,%6,%7},{%8,%9},{%0,%1,%2,%3};"
        : "+f"(c[0]), "+f"(c[1]), "+f"(c[2]), "+f"(c[3])
        : "r"(a[0]), "r"(a[1]), "r"(a[2]), "r"(a[3]), "r"(b[0]), "r"(b[1]));
}

// ---------------- tensor-core GEMM: C[M,Nc] = A@B^T + bias, split-bf16 fp32-accurate ----
// BM=128, BN=64, BK=32; 8 warps (4 rows x 2 cols), warp tile 32x32
#define AST 40   // padded row stride (bf16 elems) -> conflict-free frag loads
__global__ void __launch_bounds__(256) gemm_bf16split(
    const __nv_bfloat16* __restrict__ Ahi, const __nv_bfloat16* __restrict__ Alo,
    const __nv_bfloat16* __restrict__ Bhi, const __nv_bfloat16* __restrict__ Blo,
    const float* __restrict__ bias, float* __restrict__ C,
    int M, int Nc, int K) {
    __shared__ __nv_bfloat16 sAhi[128 * AST], sAlo[128 * AST];
    __shared__ __nv_bfloat16 sBhi[64 * AST],  sBlo[64 * AST];

    int tid = threadIdx.x, lane = tid & 31, wid = tid >> 5;
    int wr = wid >> 1, wc = wid & 1;
    int g = lane >> 2, tq = lane & 3;
    int m0 = blockIdx.y * 128, n0 = blockIdx.x * 64;

    float acc[2][4][4];
    #pragma unroll
    for (int mt = 0; mt < 2; mt++)
        #pragma unroll
        for (int nt = 0; nt < 4; nt++)
            #pragma unroll
            for (int k = 0; k < 4; k++) acc[mt][nt][k] = 0.f;

    for (int kk = 0; kk < K; kk += 32) {
        // load A tile 128x32 (hi+lo): 128 rows x 8 4-elem segs
        #pragma unroll
        for (int it = 0; it < 4; it++) {
            int s = tid + it * 256;
            int r = s >> 3, c = (s & 7) * 4;
            *(uint2*)&sAhi[r * AST + c] = *(const uint2*)&Ahi[(m0 + r) * K + kk + c];
            *(uint2*)&sAlo[r * AST + c] = *(const uint2*)&Alo[(m0 + r) * K + kk + c];
        }
        // load B tile 64x32 (hi+lo)
        #pragma unroll
        for (int it = 0; it < 2; it++) {
            int s = tid + it * 256;
            int r = s >> 3, c = (s & 7) * 4;
            *(uint2*)&sBhi[r * AST + c] = *(const uint2*)&Bhi[(n0 + r) * K + kk + c];
            *(uint2*)&sBlo[r * AST + c] = *(const uint2*)&Blo[(n0 + r) * K + kk + c];
        }
        __syncthreads();

        #pragma unroll
        for (int k16 = 0; k16 < 32; k16 += 16) {
            unsigned ahi[2][4], alo[2][4], bhi[4][2], blo[4][2];
            #pragma unroll
            for (int mt = 0; mt < 2; mt++) {
                int ra = wr * 32 + mt * 16 + g;
                const __nv_bfloat16* p = &sAhi[ra * AST + k16 + tq * 2];
                ahi[mt][0] = *(const unsigned*)p;
                ahi[mt][1] = *(const unsigned*)(p + 8 * AST);
                ahi[mt][2] = *(const unsigned*)(p + 8);
                ahi[mt][3] = *(const unsigned*)(p + 8 * AST + 8);
                const __nv_bfloat16* q = &sAlo[ra * AST + k16 + tq * 2];
                alo[mt][0] = *(const unsigned*)q;
                alo[mt][1] = *(const unsigned*)(q + 8 * AST);
                alo[mt][2] = *(const unsigned*)(q + 8);
                alo[mt][3] = *(const unsigned*)(q + 8 * AST + 8);
            }
            #pragma unroll
            for (int nt = 0; nt < 4; nt++) {
                int cb = wc * 32 + nt * 8 + g;
                const __nv_bfloat16* p = &sBhi[cb * AST + k16 + tq * 2];
                bhi[nt][0] = *(const unsigned*)p;
                bhi[nt][1] = *(const unsigned*)(p + 8);
                const __nv_bfloat16* q = &sBlo[cb * AST + k16 + tq * 2];
                blo[nt][0] = *(const unsigned*)q;
                blo[nt][1] = *(const unsigned*)(q + 8);
            }
            #pragma unroll
            for (int mt = 0; mt < 2; mt++)
                #pragma unroll
                for (int nt = 0; nt < 4; nt++) {
                    mma16816(acc[mt][nt], ahi[mt], bhi[nt]);
                    mma16816(acc[mt][nt], ahi[mt], blo[nt]);
                    mma16816(acc[mt][nt], alo[mt], bhi[nt]);
                }
        }
        __syncthreads();
    }

    #pragma unroll
    for (int mt = 0; mt < 2; mt++) {
        int r0 = m0 + wr * 32 + mt * 16 + g;
        #pragma unroll
        for (int nt = 0; nt < 4; nt++) {
            int c0 = n0 + wc * 32 + nt * 8 + tq * 2;
            float2 b2 = *(const float2*)&bias[c0];
            float2 o0 = {acc[mt][nt][0] + b2.x, acc[mt][nt][1] + b2.y};
            float2 o1 = {acc[mt][nt][2] + b2.x, acc[mt][nt][3] + b2.y};
            *(float2*)&C[r0 * Nc + c0] = o0;
            *(float2*)&C[(r0 + 8) * Nc + c0] = o1;
        }
    }
}

// ---------------- tiny projections: a_cur/a_nb for both edge types ----------------
__global__ void acoef_kernel(const float* __restrict__ x,
                             const float* __restrict__ Wa0, const float* __restrict__ Wa1,
                             float* __restrict__ ac0, float* __restrict__ an0,
                             float* __restrict__ ac1, float* __restrict__ an1) {
    __shared__ float xs[256];
    int i = blockIdx.x, tid = threadIdx.x;
    xs[tid] = x[i * 256 + tid];
    __syncthreads();
    int lane = tid & 31, wid = tid >> 5;
    #pragma unroll
    for (int oo = 0; oo < 2; oo++) {
        int o = wid + oo * 8;
        int t = o >> 3, rem = o & 7;
        int half = rem >> 2, h = rem & 3;
        const float* Wa = t ? Wa1 : Wa0;
        const float* row = Wa + h * 512 + half * 256;
        float s = 0.f;
        #pragma unroll
        for (int k = lane; k < 256; k += 32) s += xs[k] * row[k];
        #pragma unroll
        for (int off = 16; off > 0; off >>= 1) s += __shfl_down_sync(0xffffffffu, s, off);
        if (lane == 0) {
            float* dst = half ? (t ? an1 : an0) : (t ? ac1 : ac0);
            dst[i * 4 + h] = s;
        }
    }
}

// ---------------- fused transpose + mask: e[i,j] = adj[j,i]!=0 ? w[j,i] : -1 ----------------
__global__ void transpose_mask(const float* __restrict__ adj, const float* __restrict__ w,
                               float* __restrict__ e) {
    __shared__ float tile[32][33];
    int j0 = blockIdx.y * 32, i0 = blockIdx.x * 32;
    int tx = threadIdx.x, ty = threadIdx.y;
    #pragma unroll
    for (int r = 0; r < 4; r++) {
        int j = j0 + ty + r * 8;
        int idx = j * NN + i0 + tx;
        float a = adj[idx];
        tile[ty + r * 8][tx] = (a != 0.f) ? w[idx] : -1.0f;
    }
    __syncthreads();
    #pragma unroll
    for (int r = 0; r < 4; r++) {
        int i = i0 + ty + r * 8;
        e[i * NN + j0 + tx] = tile[tx][ty + r * 8];
    }
}

// ---------------- sparse softmax attention + aggregate, one block per target node ----------------
__global__ void attn_agg(const float* __restrict__ eT, const float* __restrict__ msg,
                         const float* __restrict__ acur, const float* __restrict__ anb,
                         const float* __restrict__ ba, float* __restrict__ aggout) {
    __shared__ int   jl[512];
    __shared__ float wl[512];
    __shared__ float sv[512 * 4];
    __shared__ float red[256 * 4];
    __shared__ int   warp_off[8];
    __shared__ int   sbase;
    __shared__ float hmax[4], hsum[4];

    int i = blockIdx.x;
    int tid = threadIdx.x;
    int lane = tid & 31, wid = tid >> 5;

    if (tid == 0) sbase = 0;
    for (int k = tid; k < 2048; k += 256) sv[k] = -INFINITY;
    __syncthreads();

    for (int q = 0; q < 8; q++) {
        int j = q * 256 + tid;
        float v = eT[i * NN + j];
        bool f = (v >= 0.f);
        unsigned m = __ballot_sync(0xffffffffu, f);
        int pre = __popc(m & ((1u << lane) - 1u));
        if (lane == 0) warp_off[wid] = __popc(m);
        __syncthreads();
        if (tid == 0) {
            int s = sbase;
            for (int w2 = 0; w2 < 8; w2++) { int c = warp_off[w2]; warp_off[w2] = s; s += c; }
            sbase = s;
        }
        __syncthreads();
        if (f) {
            int pos = warp_off[wid] + pre;
            if (pos < 512) { jl[pos] = j; wl[pos] = v; }
        }
        __syncthreads();
    }
    int E = sbase;
    if (E == 0) {
        aggout[i * 512 + tid] = 0.f;
        return;
    }
    if (E > 512) E = 512;

    float ac[4], bah[4];
    #pragma unroll
    for (int h = 0; h < 4; h++) { ac[h] = acur[i * 4 + h]; bah[h] = ba[h]; }

    for (int e = tid; e < E; e += 256) {
        int j = jl[e]; float w = wl[e];
        #pragma unroll
        for (int h = 0; h < 4; h++) {
            float v = anb[j * 4 + h] + ac[h] + bah[h];
            v = v > 0.f ? v : 0.2f * v;
            sv[e * 4 + h] = v * w;
        }
    }
    __syncthreads();

    #pragma unroll
    for (int h = 0; h < 4; h++) red[tid * 4 + h] = fmaxf(sv[tid * 4 + h], sv[(tid + 256) * 4 + h]);
    __syncthreads();
    for (int off = 128; off > 0; off >>= 1) {
        if (tid < off)
            #pragma unroll
            for (int h = 0; h < 4; h++) red[tid * 4 + h] = fmaxf(red[tid * 4 + h], red[(tid + off) * 4 + h]);
        __syncthreads();
    }
    if (tid < 4) hmax[tid] = red[tid];
    __syncthreads();

    for (int e = tid; e < 512; e += 256) {
        #pragma unroll
        for (int h = 0; h < 4; h++) sv[e * 4 + h] = expf(sv[e * 4 + h] - hmax[h]);
    }
    __syncthreads();

    #pragma unroll
    for (int h = 0; h < 4; h++) red[tid * 4 + h] = sv[tid * 4 + h] + sv[(tid + 256) * 4 + h];
    __syncthreads();
    for (int off = 128; off > 0; off >>= 1) {
        if (tid < off)
            #pragma unroll
            for (int h = 0; h < 4; h++) red[tid * 4 + h] += red[(tid + off) * 4 + h];
        __syncthreads();
    }
    if (tid < 4) hsum[tid] = red[tid];
    __syncthreads();

    for (int e = tid; e < E; e += 256) {
        #pragma unroll
        for (int h = 0; h < 4; h++) sv[e * 4 + h] *= (1.f / hsum[h]);
    }
    __syncthreads();

    int d = tid, h = d >> 6;
    float acc = 0.f;
    for (int e = 0; e < E; e++) acc += sv[e * 4 + h] * msg[jl[e] * 256 + d];
    aggout[i * 512 + d] = acc;
}

// ---------------- GRU gates + LayerNorm ----------------
__global__ void gru_ln(const float* __restrict__ gi_, const float* __restrict__ gh_,
                       const float* __restrict__ x, const float* __restrict__ g,
                       const float* __restrict__ b, float* __restrict__ out) {
    int i = blockIdx.x, d = threadIdx.x;
    const float* gi = gi_ + i * 768;
    const float* gh = gh_ + i * 768;
    float r = 1.f / (1.f + expf(-(gi[d] + gh[d])));
    float z = 1.f / (1.f + expf(-(gi[256 + d] + gh[256 + d])));
    float n = tanhf(gi[512 + d] + r * gh[512 + d]);
    float hv = (1.f - z) * n + z * x[i * 256 + d];

    __shared__ float ssum[8], ssq[8];
    __shared__ float mu_s, rs_s;
    float s = hv, q = hv * hv;
    #pragma unroll
    for (int off = 16; off > 0; off >>= 1) {
        s += __shfl_down_sync(0xffffffffu, s, off);
        q += __shfl_down_sync(0xffffffffu, q, off);
    }
    int lane = d & 31, wid = d >> 5;
    if (lane == 0) { ssum[wid] = s; ssq[wid] = q; }
    __syncthreads();
    if (d == 0) {
        float S = 0.f, Q = 0.f;
        for (int w2 = 0; w2 < 8; w2++) { S += ssum[w2]; Q += ssq[w2]; }
        float mu = S / 256.f;
        float var = Q / 256.f - mu * mu;
        mu_s = mu;
        rs_s = rsqrtf(var + 1e-5f);
    }
    __syncthreads();
    out[i * 256 + d] = (hv - mu_s) * rs_s * g[d] + b[d];
}

// ---------------- host orchestration ----------------
extern "C" void kernel_launch(void* const* d_in, const int* in_sizes, int n_in,
                              void* d_out, int out_size) {
    const float* x    = (const float*)d_in[0];
    const float* adj0 = (const float*)d_in[1];
    const float* adj1 = (const float*)d_in[2];
    const float* w0   = (const float*)d_in[3];
    const float* w1   = (const float*)d_in[4];
    const float* bm0  = (const float*)d_in[6];
    const float* Wa0  = (const float*)d_in[7];
    const float* ba0  = (const float*)d_in[8];
    const float* bm1  = (const float*)d_in[10];
    const float* Wa1  = (const float*)d_in[11];
    const float* ba1  = (const float*)d_in[12];
    const float* bih  = (const float*)d_in[15];
    const float* bhh  = (const float*)d_in[16];
    const float* lng  = (const float*)d_in[17];
    const float* lnb  = (const float*)d_in[18];
    const float* Wm0  = (const float*)d_in[5];
    const float* Wm1  = (const float*)d_in[9];
    const float* wih  = (const float*)d_in[13];
    const float* whh  = (const float*)d_in[14];
    float* out = (float*)d_out;

    float *msg0, *msg1, *e0, *e1, *agg, *gi, *gh, *ac0, *an0, *ac1, *an1;
    cudaGetSymbolAddress((void**)&msg0, g_msg0);
    cudaGetSymbolAddress((void**)&msg1, g_msg1);
    cudaGetSymbolAddress((void**)&e0,   g_e0);
    cudaGetSymbolAddress((void**)&e1,   g_e1);
    cudaGetSymbolAddress((void**)&agg,  g_agg);
    cudaGetSymbolAddress((void**)&gi,   g_gi);
    cudaGetSymbolAddress((void**)&gh,   g_gh);
    cudaGetSymbolAddress((void**)&ac0,  g_ac0);
    cudaGetSymbolAddress((void**)&an0,  g_an0);
    cudaGetSymbolAddress((void**)&ac1,  g_ac1);
    cudaGetSymbolAddress((void**)&an1,  g_an1);

    __nv_bfloat16 *xhi, *xlo, *ahi, *alo, *wm0hi, *wm0lo, *wm1hi, *wm1lo,
                  *wihhi, *wihlo, *whhhi, *whhlo;
    cudaGetSymbolAddress((void**)&xhi,   g_xhi);
    cudaGetSymbolAddress((void**)&xlo,   g_xlo);
    cudaGetSymbolAddress((void**)&ahi,   g_ahi);
    cudaGetSymbolAddress((void**)&alo,   g_alo);
    cudaGetSymbolAddress((void**)&wm0hi, g_wm0hi);
    cudaGetSymbolAddress((void**)&wm0lo, g_wm0lo);
    cudaGetSymbolAddress((void**)&wm1hi, g_wm1hi);
    cudaGetSymbolAddress((void**)&wm1lo, g_wm1lo);
    cudaGetSymbolAddress((void**)&wihhi, g_wihhi);
    cudaGetSymbolAddress((void**)&wihlo, g_wihlo);
    cudaGetSymbolAddress((void**)&whhhi, g_whhhi);
    cudaGetSymbolAddress((void**)&whhlo, g_whhlo);

    // split operands to (hi, lo) bf16
    split_bf16<<<(NN * 256 / 4 + 255) / 256, 256>>>(x,   xhi,   xlo,   NN * 256 / 4);
    split_bf16<<<(256 * 256 / 4 + 255) / 256, 256>>>(Wm0, wm0hi, wm0lo, 256 * 256 / 4);
    split_bf16<<<(256 * 256 / 4 + 255) / 256, 256>>>(Wm1, wm1hi, wm1lo, 256 * 256 / 4);
    split_bf16<<<(768 * 512 / 4 + 255) / 256, 256>>>(wih, wihhi, wihlo, 768 * 512 / 4);
    split_bf16<<<(768 * 256 / 4 + 255) / 256, 256>>>(whh, whhhi, whhlo, 768 * 256 / 4);

    acoef_kernel<<<NN, 256>>>(x, Wa0, Wa1, ac0, an0, ac1, an1);

    // msg GEMMs: [2048,256] = x @ Wm^T
    gemm_bf16split<<<dim3(4, 16), 256>>>(xhi, xlo, wm0hi, wm0lo, bm0, msg0, NN, 256, 256);
    gemm_bf16split<<<dim3(4, 16), 256>>>(xhi, xlo, wm1hi, wm1lo, bm1, msg1, NN, 256, 256);

    transpose_mask<<<dim3(64, 64), dim3(32, 8)>>>(adj0, w0, e0);
    transpose_mask<<<dim3(64, 64), dim3(32, 8)>>>(adj1, w1, e1);

    attn_agg<<<NN, 256>>>(e0, msg0, ac0, an0, ba0, agg);
    attn_agg<<<NN, 256>>>(e1, msg1, ac1, an1, ba1, agg + 256);

    // GRU GEMMs on tensor cores
    split_bf16<<<(NN * 512 / 4 + 255) / 256, 256>>>(agg, ahi, alo, NN * 512 / 4);
    gemm_bf16split<<<dim3(12, 16), 256>>>(ahi, alo, wihhi, wihlo, bih, gi, NN, 768, 512);
    gemm_bf16split<<<dim3(12, 16), 256>>>(xhi, xlo, whhhi, whhlo, bhh, gh, NN, 768, 256);

    gru_ln<<<NN, 256>>>(gi, gh, x, lng, lnb, out);
}

// round 7
// speedup vs baseline: 1.9514x; 1.1891x over previous
#include <cuda_runtime.h>
#include <cuda_bf16.h>
#include <math.h>

#define NN 2048
#define DD 256

// ---------------- scratch (device globals; no allocation) ----------------
__device__ float g_msg[NN * 512];       // [msg0 | msg1] interleaved by column halves
__device__ float g_e0[NN * NN];
__device__ float g_e1[NN * NN];
__device__ float g_agg[NN * 512];       // [agg0 | agg1]
__device__ float g_gi[NN * 768];
__device__ float g_gh[NN * 768];
__device__ float g_ac0[NN * 4];
__device__ float g_an0[NN * 4];
__device__ float g_ac1[NN * 4];
__device__ float g_an1[NN * 4];
__device__ float g_bm[512];             // [bm0 | bm1]

// bf16 split operands
__device__ __nv_bfloat16 g_xhi[NN * 256],  g_xlo[NN * 256];
__device__ __nv_bfloat16 g_ahi[NN * 512],  g_alo[NN * 512];
__device__ __nv_bfloat16 g_wmhi[512 * 256], g_wmlo[512 * 256];   // [Wm0 ; Wm1]
__device__ __nv_bfloat16 g_wihhi[768 * 512], g_wihlo[768 * 512];
__device__ __nv_bfloat16 g_whhhi[768 * 256], g_whhlo[768 * 256];

// ---------------- fused split fp32 -> (hi, lo) bf16 for 5 tensors ----------------
struct SJ { const float* src; __nv_bfloat16* hi; __nv_bfloat16* lo; int n4; };

__device__ __forceinline__ void do_split(const SJ& j) {
    int i = blockIdx.x * 256 + threadIdx.x;
    if (i >= j.n4) return;
    float4 v = ((const float4*)j.src)[i];
    float vv[4] = {v.x, v.y, v.z, v.w};
    __nv_bfloat16 h[4], l[4];
    #pragma unroll
    for (int k = 0; k < 4; k++) {
        h[k] = __float2bfloat16(vv[k]);
        l[k] = __float2bfloat16(vv[k] - __bfloat162float(h[k]));
    }
    *(uint2*)&j.hi[i * 4] = *(uint2*)h;
    *(uint2*)&j.lo[i * 4] = *(uint2*)l;
}

__global__ void split_all(SJ j0, SJ j1, SJ j2, SJ j3, SJ j4) {
    switch (blockIdx.y) {
        case 0: do_split(j0); break;
        case 1: do_split(j1); break;
        case 2: do_split(j2); break;
        case 3: do_split(j3); break;
        default: do_split(j4); break;
    }
}

__global__ void split_one(const float* __restrict__ src,
                          __nv_bfloat16* __restrict__ hi,
                          __nv_bfloat16* __restrict__ lo, int n4) {
    SJ j{src, hi, lo, n4};
    do_split(j);
}

__global__ void bmcat(const float* __restrict__ b0, const float* __restrict__ b1,
                      float* __restrict__ o) {
    int t = threadIdx.x;
    o[t] = b0[t];
    o[t + 256] = b1[t];
}

// ---------------- mma helper ----------------
__device__ __forceinline__ void mma16816(float* c, const unsigned* a, const unsigned* b) {
    asm volatile(
        "mma.sync.aligned.m16n8k16.row.col.f32.bf16.bf16.f32 "
        "{%0,%1,%2,%3},{%4,%5,%6,%7},{%8,%9},{%0,%1,%2,%3};"
        : "+f"(c[0]), "+f"(c[1]), "+f"(c[2]), "+f"(c[3])
        : "r"(a[0]), "r"(a[1]), "r"(a[2]), "r"(a[3]), "r"(b[0]), "r"(b[1]));
}

// ---------------- tensor-core GEMM with cp.async double buffering ----------------
// C[M,Nc] = A@B^T + bias; split-bf16 (hihi+hilo+lohi) fp32-accurate.
// BM=128, BN=64, BK=32; 8 warps (4x2), warp tile 32x32.
#define AST 40
#define ASZ (128 * AST)
#define BSZ (64 * AST)
#define GEMM_SMEM ((4 * ASZ + 4 * BSZ) * 2)

__global__ void __launch_bounds__(256) gemm_bf16split(
    const __nv_bfloat16* __restrict__ Ahi, const __nv_bfloat16* __restrict__ Alo,
    const __nv_bfloat16* __restrict__ Bhi, const __nv_bfloat16* __restrict__ Blo,
    const float* __restrict__ bias, float* __restrict__ C,
    int M, int Nc, int K) {
    extern __shared__ __nv_bfloat16 smem[];
    __nv_bfloat16* sA = smem;             // [stage][hi/lo][ASZ]
    __nv_bfloat16* sB = smem + 4 * ASZ;   // [stage][hi/lo][BSZ]

    int tid = threadIdx.x, lane = tid & 31, wid = tid >> 5;
    int wr = wid >> 1, wc = wid & 1;
    int g = lane >> 2, tq = lane & 3;
    int m0 = blockIdx.y * 128, n0 = blockIdx.x * 64;

    float acc[2][4][4] = {};

    auto issue = [&](int kk, int st) {
        // A tile 128x32, 512 16B chunks: 2 per thread (hi and lo each)
        #pragma unroll
        for (int it = 0; it < 2; it++) {
            int ch = tid + it * 256;
            int r = ch >> 2, c = (ch & 3) * 8;
            unsigned dh = (unsigned)__cvta_generic_to_shared(&sA[(st * 2 + 0) * ASZ + r * AST + c]);
            unsigned dl = (unsigned)__cvta_generic_to_shared(&sA[(st * 2 + 1) * ASZ + r * AST + c]);
            asm volatile("cp.async.cg.shared.global [%0],[%1],16;" :: "r"(dh), "l"(&Ahi[(m0 + r) * K + kk + c]));
            asm volatile("cp.async.cg.shared.global [%0],[%1],16;" :: "r"(dl), "l"(&Alo[(m0 + r) * K + kk + c]));
        }
        // B tile 64x32, 256 chunks: 1 per thread (hi and lo each)
        {
            int r = tid >> 2, c = (tid & 3) * 8;
            unsigned dh = (unsigned)__cvta_generic_to_shared(&sB[(st * 2 + 0) * BSZ + r * AST + c]);
            unsigned dl = (unsigned)__cvta_generic_to_shared(&sB[(st * 2 + 1) * BSZ + r * AST + c]);
            asm volatile("cp.async.cg.shared.global [%0],[%1],16;" :: "r"(dh), "l"(&Bhi[(n0 + r) * K + kk + c]));
            asm volatile("cp.async.cg.shared.global [%0],[%1],16;" :: "r"(dl), "l"(&Blo[(n0 + r) * K + kk + c]));
        }
    };

    auto compute = [&](int st) {
        const __nv_bfloat16* Ah = sA + (st * 2 + 0) * ASZ;
        const __nv_bfloat16* Al = sA + (st * 2 + 1) * ASZ;
        const __nv_bfloat16* Bh = sB + (st * 2 + 0) * BSZ;
        const __nv_bfloat16* Bl = sB + (st * 2 + 1) * BSZ;
        #pragma unroll
        for (int k16 = 0; k16 < 32; k16 += 16) {
            unsigned ahi[2][4], alo[2][4], bhi[4][2], blo[4][2];
            #pragma unroll
            for (int mt = 0; mt < 2; mt++) {
                int ra = wr * 32 + mt * 16 + g;
                const __nv_bfloat16* p = &Ah[ra * AST + k16 + tq * 2];
                ahi[mt][0] = *(const unsigned*)p;
                ahi[mt][1] = *(const unsigned*)(p + 8 * AST);
                ahi[mt][2] = *(const unsigned*)(p + 8);
                ahi[mt][3] = *(const unsigned*)(p + 8 * AST + 8);
                const __nv_bfloat16* q = &Al[ra * AST + k16 + tq * 2];
                alo[mt][0] = *(const unsigned*)q;
                alo[mt][1] = *(const unsigned*)(q + 8 * AST);
                alo[mt][2] = *(const unsigned*)(q + 8);
                alo[mt][3] = *(const unsigned*)(q + 8 * AST + 8);
            }
            #pragma unroll
            for (int nt = 0; nt < 4; nt++) {
                int cb = wc * 32 + nt * 8 + g;
                const __nv_bfloat16* p = &Bh[cb * AST + k16 + tq * 2];
                bhi[nt][0] = *(const unsigned*)p;
                bhi[nt][1] = *(const unsigned*)(p + 8);
                const __nv_bfloat16* q = &Bl[cb * AST + k16 + tq * 2];
                blo[nt][0] = *(const unsigned*)q;
                blo[nt][1] = *(const unsigned*)(q + 8);
            }
            #pragma unroll
            for (int mt = 0; mt < 2; mt++)
                #pragma unroll
                for (int nt = 0; nt < 4; nt++) {
                    mma16816(acc[mt][nt], ahi[mt], bhi[nt]);
                    mma16816(acc[mt][nt], ahi[mt], blo[nt]);
                    mma16816(acc[mt][nt], alo[mt], bhi[nt]);
                }
        }
    };

    int nk = K / 32;
    issue(0, 0);
    asm volatile("cp.async.commit_group;");
    for (int kt = 0; kt < nk; kt++) {
        if (kt + 1 < nk) {
            issue((kt + 1) * 32, (kt + 1) & 1);
            asm volatile("cp.async.commit_group;");
            asm volatile("cp.async.wait_group 1;");
        } else {
            asm volatile("cp.async.wait_group 0;");
        }
        __syncthreads();
        compute(kt & 1);
        __syncthreads();
    }

    #pragma unroll
    for (int mt = 0; mt < 2; mt++) {
        int r0 = m0 + wr * 32 + mt * 16 + g;
        #pragma unroll
        for (int nt = 0; nt < 4; nt++) {
            int c0 = n0 + wc * 32 + nt * 8 + tq * 2;
            float2 b2 = *(const float2*)&bias[c0];
            float2 o0 = {acc[mt][nt][0] + b2.x, acc[mt][nt][1] + b2.y};
            float2 o1 = {acc[mt][nt][2] + b2.x, acc[mt][nt][3] + b2.y};
            *(float2*)&C[r0 * Nc + c0] = o0;
            *(float2*)&C[(r0 + 8) * Nc + c0] = o1;
        }
    }
}

// ---------------- tiny projections: a_cur/a_nb for both edge types ----------------
__global__ void acoef_kernel(const float* __restrict__ x,
                             const float* __restrict__ Wa0, const float* __restrict__ Wa1,
                             float* __restrict__ ac0, float* __restrict__ an0,
                             float* __restrict__ ac1, float* __restrict__ an1) {
    __shared__ float xs[256];
    int i = blockIdx.x, tid = threadIdx.x;
    xs[tid] = x[i * 256 + tid];
    __syncthreads();
    int lane = tid & 31, wid = tid >> 5;
    #pragma unroll
    for (int oo = 0; oo < 2; oo++) {
        int o = wid + oo * 8;
        int t = o >> 3, rem = o & 7;
        int half = rem >> 2, h = rem & 3;
        const float* Wa = t ? Wa1 : Wa0;
        const float* row = Wa + h * 512 + half * 256;
        float s = 0.f;
        #pragma unroll
        for (int k = lane; k < 256; k += 32) s += xs[k] * row[k];
        #pragma unroll
        for (int off = 16; off > 0; off >>= 1) s += __shfl_down_sync(0xffffffffu, s, off);
        if (lane == 0) {
            float* dst = half ? (t ? an1 : an0) : (t ? ac1 : ac0);
            dst[i * 4 + h] = s;
        }
    }
}

// ---------------- fused transpose + mask, both edge types (z dim) ----------------
__global__ void transpose_mask2(const float* __restrict__ adj0, const float* __restrict__ w0,
                                float* __restrict__ e0,
                                const float* __restrict__ adj1, const float* __restrict__ w1,
                                float* __restrict__ e1) {
    const float* adj = blockIdx.z ? adj1 : adj0;
    const float* w   = blockIdx.z ? w1   : w0;
    float*       e   = blockIdx.z ? e1   : e0;
    __shared__ float tile[32][33];
    int j0 = blockIdx.y * 32, i0 = blockIdx.x * 32;
    int tx = threadIdx.x, ty = threadIdx.y;
    #pragma unroll
    for (int r = 0; r < 4; r++) {
        int j = j0 + ty + r * 8;
        int idx = j * NN + i0 + tx;
        float a = adj[idx];
        tile[ty + r * 8][tx] = (a != 0.f) ? w[idx] : -1.0f;
    }
    __syncthreads();
    #pragma unroll
    for (int r = 0; r < 4; r++) {
        int i = i0 + ty + r * 8;
        e[i * NN + j0 + tx] = tile[tx][ty + r * 8];
    }
}

// ---------------- sparse softmax attention + aggregate, both types (y dim) ----------------
__global__ void attn_agg2(const float* __restrict__ eT0, const float* __restrict__ eT1,
                          const float* __restrict__ msgcat,
                          const float* __restrict__ ac0_, const float* __restrict__ an0_,
                          const float* __restrict__ ac1_, const float* __restrict__ an1_,
                          const float* __restrict__ ba0, const float* __restrict__ ba1,
                          float* __restrict__ aggout) {
    __shared__ int   jl[512];
    __shared__ float wl[512];
    __shared__ float sv[512 * 4];
    __shared__ float red[256 * 4];
    __shared__ int   warp_off[8];
    __shared__ int   sbase;
    __shared__ float hmax[4], hsum[4];

    int t = blockIdx.y;
    const float* eT   = t ? eT1 : eT0;
    const float* acur = t ? ac1_ : ac0_;
    const float* anb  = t ? an1_ : an0_;
    const float* ba   = t ? ba1 : ba0;
    const float* msg  = msgcat + t * 256;    // row stride 512

    int i = blockIdx.x;
    int tid = threadIdx.x;
    int lane = tid & 31, wid = tid >> 5;

    if (tid == 0) sbase = 0;
    for (int k = tid; k < 2048; k += 256) sv[k] = -INFINITY;
    __syncthreads();

    for (int q = 0; q < 8; q++) {
        int j = q * 256 + tid;
        float v = eT[i * NN + j];
        bool f = (v >= 0.f);
        unsigned m = __ballot_sync(0xffffffffu, f);
        int pre = __popc(m & ((1u << lane) - 1u));
        if (lane == 0) warp_off[wid] = __popc(m);
        __syncthreads();
        if (tid == 0) {
            int s = sbase;
            for (int w2 = 0; w2 < 8; w2++) { int c = warp_off[w2]; warp_off[w2] = s; s += c; }
            sbase = s;
        }
        __syncthreads();
        if (f) {
            int pos = warp_off[wid] + pre;
            if (pos < 512) { jl[pos] = j; wl[pos] = v; }
        }
        __syncthreads();
    }
    int E = sbase;
    if (E == 0) {
        aggout[i * 512 + t * 256 + tid] = 0.f;
        return;
    }
    if (E > 512) E = 512;

    float ac[4], bah[4];
    #pragma unroll
    for (int h = 0; h < 4; h++) { ac[h] = acur[i * 4 + h]; bah[h] = ba[h]; }

    for (int e = tid; e < E; e += 256) {
        int j = jl[e]; float w = wl[e];
        #pragma unroll
        for (int h = 0; h < 4; h++) {
            float v = anb[j * 4 + h] + ac[h] + bah[h];
            v = v > 0.f ? v : 0.2f * v;
            sv[e * 4 + h] = v * w;
        }
    }
    __syncthreads();

    #pragma unroll
    for (int h = 0; h < 4; h++) red[tid * 4 + h] = fmaxf(sv[tid * 4 + h], sv[(tid + 256) * 4 + h]);
    __syncthreads();
    for (int off = 128; off > 0; off >>= 1) {
        if (tid < off)
            #pragma unroll
            for (int h = 0; h < 4; h++) red[tid * 4 + h] = fmaxf(red[tid * 4 + h], red[(tid + off) * 4 + h]);
        __syncthreads();
    }
    if (tid < 4) hmax[tid] = red[tid];
    __syncthreads();

    for (int e = tid; e < 512; e += 256) {
        #pragma unroll
        for (int h = 0; h < 4; h++) sv[e * 4 + h] = expf(sv[e * 4 + h] - hmax[h]);
    }
    __syncthreads();

    #pragma unroll
    for (int h = 0; h < 4; h++) red[tid * 4 + h] = sv[tid * 4 + h] + sv[(tid + 256) * 4 + h];
    __syncthreads();
    for (int off = 128; off > 0; off >>= 1) {
        if (tid < off)
            #pragma unroll
            for (int h = 0; h < 4; h++) red[tid * 4 + h] += red[(tid + off) * 4 + h];
        __syncthreads();
    }
    if (tid < 4) hsum[tid] = red[tid];
    __syncthreads();

    for (int e = tid; e < E; e += 256) {
        #pragma unroll
        for (int h = 0; h < 4; h++) sv[e * 4 + h] *= (1.f / hsum[h]);
    }
    __syncthreads();

    int d = tid, h = d >> 6;
    float acc = 0.f;
    for (int e = 0; e < E; e++) acc += sv[e * 4 + h] * msg[jl[e] * 512 + d];
    aggout[i * 512 + t * 256 + d] = acc;
}

// ---------------- GRU gates + LayerNorm ----------------
__global__ void gru_ln(const float* __restrict__ gi_, const float* __restrict__ gh_,
                       const float* __restrict__ x, const float* __restrict__ g,
                       const float* __restrict__ b, float* __restrict__ out) {
    int i = blockIdx.x, d = threadIdx.x;
    const float* gi = gi_ + i * 768;
    const float* gh = gh_ + i * 768;
    float r = 1.f / (1.f + expf(-(gi[d] + gh[d])));
    float z = 1.f / (1.f + expf(-(gi[256 + d] + gh[256 + d])));
    float n = tanhf(gi[512 + d] + r * gh[512 + d]);
    float hv = (1.f - z) * n + z * x[i * 256 + d];

    __shared__ float ssum[8], ssq[8];
    __shared__ float mu_s, rs_s;
    float s = hv, q = hv * hv;
    #pragma unroll
    for (int off = 16; off > 0; off >>= 1) {
        s += __shfl_down_sync(0xffffffffu, s, off);
        q += __shfl_down_sync(0xffffffffu, q, off);
    }
    int lane = d & 31, wid = d >> 5;
    if (lane == 0) { ssum[wid] = s; ssq[wid] = q; }
    __syncthreads();
    if (d == 0) {
        float S = 0.f, Q = 0.f;
        for (int w2 = 0; w2 < 8; w2++) { S += ssum[w2]; Q += ssq[w2]; }
        float mu = S / 256.f;
        float var = Q / 256.f - mu * mu;
        mu_s = mu;
        rs_s = rsqrtf(var + 1e-5f);
    }
    __syncthreads();
    out[i * 256 + d] = (hv - mu_s) * rs_s * g[d] + b[d];
}

// ---------------- host orchestration ----------------
extern "C" void kernel_launch(void* const* d_in, const int* in_sizes, int n_in,
                              void* d_out, int out_size) {
    const float* x    = (const float*)d_in[0];
    const float* adj0 = (const float*)d_in[1];
    const float* adj1 = (const float*)d_in[2];
    const float* w0   = (const float*)d_in[3];
    const float* w1   = (const float*)d_in[4];
    const float* Wm0  = (const float*)d_in[5];
    const float* bm0  = (const float*)d_in[6];
    const float* Wa0  = (const float*)d_in[7];
    const float* ba0  = (const float*)d_in[8];
    const float* Wm1  = (const float*)d_in[9];
    const float* bm1  = (const float*)d_in[10];
    const float* Wa1  = (const float*)d_in[11];
    const float* ba1  = (const float*)d_in[12];
    const float* wih  = (const float*)d_in[13];
    const float* whh  = (const float*)d_in[14];
    const float* bih  = (const float*)d_in[15];
    const float* bhh  = (const float*)d_in[16];
    const float* lng  = (const float*)d_in[17];
    const float* lnb  = (const float*)d_in[18];
    float* out = (float*)d_out;

    float *msg, *e0, *e1, *agg, *gi, *gh, *ac0, *an0, *ac1, *an1, *bm;
    cudaGetSymbolAddress((void**)&msg, g_msg);
    cudaGetSymbolAddress((void**)&e0,  g_e0);
    cudaGetSymbolAddress((void**)&e1,  g_e1);
    cudaGetSymbolAddress((void**)&agg, g_agg);
    cudaGetSymbolAddress((void**)&gi,  g_gi);
    cudaGetSymbolAddress((void**)&gh,  g_gh);
    cudaGetSymbolAddress((void**)&ac0, g_ac0);
    cudaGetSymbolAddress((void**)&an0, g_an0);
    cudaGetSymbolAddress((void**)&ac1, g_ac1);
    cudaGetSymbolAddress((void**)&an1, g_an1);
    cudaGetSymbolAddress((void**)&bm,  g_bm);

    __nv_bfloat16 *xhi, *xlo, *ahi, *alo, *wmhi, *wmlo, *wihhi, *wihlo, *whhhi, *whhlo;
    cudaGetSymbolAddress((void**)&xhi,   g_xhi);
    cudaGetSymbolAddress((void**)&xlo,   g_xlo);
    cudaGetSymbolAddress((void**)&ahi,   g_ahi);
    cudaGetSymbolAddress((void**)&alo,   g_alo);
    cudaGetSymbolAddress((void**)&wmhi,  g_wmhi);
    cudaGetSymbolAddress((void**)&wmlo,  g_wmlo);
    cudaGetSymbolAddress((void**)&wihhi, g_wihhi);
    cudaGetSymbolAddress((void**)&wihlo, g_wihlo);
    cudaGetSymbolAddress((void**)&whhhi, g_whhhi);
    cudaGetSymbolAddress((void**)&whhlo, g_whhlo);

    cudaFuncSetAttribute(gemm_bf16split,
                         cudaFuncAttributeMaxDynamicSharedMemorySize, GEMM_SMEM);

    // fused splits: x, Wm0 (rows 0-255 of wm), Wm1 (rows 256-511), wih, whh
    SJ j0{x,   xhi,   xlo,   NN * 256 / 4};
    SJ j1{Wm0, wmhi,  wmlo,  256 * 256 / 4};
    SJ j2{Wm1, wmhi + 256 * 256, wmlo + 256 * 256, 256 * 256 / 4};
    SJ j3{wih, wihhi, wihlo, 768 * 512 / 4};
    SJ j4{whh, whhhi, whhlo, 768 * 256 / 4};
    split_all<<<dim3(512, 5), 256>>>(j0, j1, j2, j3, j4);
    bmcat<<<1, 256>>>(bm0, bm1, bm);

    acoef_kernel<<<NN, 256>>>(x, Wa0, Wa1, ac0, an0, ac1, an1);

    // merged msg GEMM: [2048,512] = x @ [Wm0;Wm1]^T
    gemm_bf16split<<<dim3(8, 16), 256, GEMM_SMEM>>>(xhi, xlo, wmhi, wmlo, bm, msg, NN, 512, 256);

    transpose_mask2<<<dim3(64, 64, 2), dim3(32, 8)>>>(adj0, w0, e0, adj1, w1, e1);

    attn_agg2<<<dim3(NN, 2), 256>>>(e0, e1, msg, ac0, an0, ac1, an1, ba0, ba1, agg);

    // GRU GEMMs
    split_one<<<(NN * 512 / 4 + 255) / 256, 256>>>(agg, ahi, alo, NN * 512 / 4);
    gemm_bf16split<<<dim3(12, 16), 256, GEMM_SMEM>>>(ahi, alo, wihhi, wihlo, bih, gi, NN, 768, 512);
    gemm_bf16split<<<dim3(12, 16), 256, GEMM_SMEM>>>(xhi, xlo, whhhi, whhlo, bhh, gh, NN, 768, 256);

    gru_ln<<<NN, 256>>>(gi, gh, x, lng, lnb, out);
}

// round 9
// speedup vs baseline: 2.2294x; 1.1425x over previous
#include <cuda_runtime.h>
#include <cuda_bf16.h>
#include <math.h>

#define NN 2048
#define DD 256

// ---------------- scratch (device globals; no allocation) ----------------
__device__ float g_msg[NN * 512];       // [msg0 | msg1] by column halves
__device__ float g_e0[NN * NN];
__device__ float g_e1[NN * NN];
__device__ float g_gi[NN * 768];
__device__ float g_gh[NN * 768];
__device__ float g_ac0[NN * 4];
__device__ float g_an0[NN * 4];
__device__ float g_ac1[NN * 4];
__device__ float g_an1[NN * 4];
__device__ float g_bm[512];             // [bm0 | bm1]

// bf16 split operands
__device__ __nv_bfloat16 g_xhi[NN * 256],  g_xlo[NN * 256];
__device__ __nv_bfloat16 g_ahi[NN * 512],  g_alo[NN * 512];      // agg in bf16 hi/lo
__device__ __nv_bfloat16 g_wmhi[512 * 256], g_wmlo[512 * 256];   // [Wm0 ; Wm1]
__device__ __nv_bfloat16 g_wihhi[768 * 512], g_wihlo[768 * 512];
__device__ __nv_bfloat16 g_whhhi[768 * 256], g_whhlo[768 * 256];

// ---------------- split helper ----------------
__device__ __forceinline__ void do_split(int blk, const float* __restrict__ src,
                                         __nv_bfloat16* __restrict__ hi,
                                         __nv_bfloat16* __restrict__ lo, int n4) {
    int i = blk * 256 + threadIdx.x;
    if (i >= n4) return;
    float4 v = ((const float4*)src)[i];
    float vv[4] = {v.x, v.y, v.z, v.w};
    __nv_bfloat16 h[4], l[4];
    #pragma unroll
    for (int k = 0; k < 4; k++) {
        h[k] = __float2bfloat16(vv[k]);
        l[k] = __float2bfloat16(vv[k] - __bfloat162float(h[k]));
    }
    *(uint2*)&hi[i * 4] = *(uint2*)h;
    *(uint2*)&lo[i * 4] = *(uint2*)l;
}

// ---------------- phase1 mega-kernel ----------------
// blocks [0, 8192):           transpose+mask for both edge types
// blocks [8192, 10240):       acoef (a_cur / a_nb projections)
// blocks [10240, 11456):      bf16 splits of x, Wm0, Wm1, wih, whh
// block 11456:                bmcat
#define P1_T    8192
#define P1_AC   (P1_T + 2048)
#define P1_SPX  (P1_AC)                 // x: 512 blocks
#define P1_SPW0 (P1_SPX + 512)          // Wm0: 64
#define P1_SPW1 (P1_SPW0 + 64)          // Wm1: 64
#define P1_SPIH (P1_SPW1 + 64)          // wih: 384
#define P1_SPHH (P1_SPIH + 384)         // whh: 192
#define P1_BM   (P1_SPHH + 192)
#define P1_GRID (P1_BM + 1)

__global__ void phase1(const float* __restrict__ x,
                       const float* __restrict__ adj0, const float* __restrict__ w0,
                       const float* __restrict__ adj1, const float* __restrict__ w1,
                       const float* __restrict__ Wa0, const float* __restrict__ Wa1,
                       const float* __restrict__ Wm0, const float* __restrict__ Wm1,
                       const float* __restrict__ wih, const float* __restrict__ whh,
                       const float* __restrict__ bm0, const float* __restrict__ bm1,
                       float* __restrict__ e0, float* __restrict__ e1,
                       float* __restrict__ ac0, float* __restrict__ an0,
                       float* __restrict__ ac1, float* __restrict__ an1,
                       __nv_bfloat16* __restrict__ xhi, __nv_bfloat16* __restrict__ xlo,
                       __nv_bfloat16* __restrict__ wmhi, __nv_bfloat16* __restrict__ wmlo,
                       __nv_bfloat16* __restrict__ wihhi, __nv_bfloat16* __restrict__ wihlo,
                       __nv_bfloat16* __restrict__ whhhi, __nv_bfloat16* __restrict__ whhlo,
                       float* __restrict__ bm) {
    int b = blockIdx.x;
    int tid = threadIdx.x;

    if (b < P1_T) {
        // ---- transpose + mask ----
        int t = b >> 12;                 // 4096 tiles per edge type
        int rem = b & 4095;
        int i0 = (rem & 63) * 32, j0 = (rem >> 6) * 32;
        const float* adj = t ? adj1 : adj0;
        const float* w   = t ? w1   : w0;
        float*       e   = t ? e1   : e0;
        __shared__ float tile[32][33];
        int tx = tid & 31, ty = tid >> 5;    // 32 x 8
        #pragma unroll
        for (int r = 0; r < 4; r++) {
            int j = j0 + ty + r * 8;
            int idx = j * NN + i0 + tx;
            float a = adj[idx];
            tile[ty + r * 8][tx] = (a != 0.f) ? w[idx] : -1.0f;
        }
        __syncthreads();
        #pragma unroll
        for (int r = 0; r < 4; r++) {
            int i = i0 + ty + r * 8;
            e[i * NN + j0 + tx] = tile[tx][ty + r * 8];
        }
        return;
    }
    if (b < P1_AC) {
        // ---- acoef ----
        int i = b - P1_T;
        __shared__ float xs[256];
        xs[tid] = x[i * 256 + tid];
        __syncthreads();
        int lane = tid & 31, wid = tid >> 5;
        #pragma unroll
        for (int oo = 0; oo < 2; oo++) {
            int o = wid + oo * 8;
            int t = o >> 3, rem = o & 7;
            int half = rem >> 2, h = rem & 3;
            const float* Wa = t ? Wa1 : Wa0;
            const float* row = Wa + h * 512 + half * 256;
            float s = 0.f;
            #pragma unroll
            for (int k = lane; k < 256; k += 32) s += xs[k] * row[k];
            #pragma unroll
            for (int off = 16; off > 0; off >>= 1) s += __shfl_down_sync(0xffffffffu, s, off);
            if (lane == 0) {
                float* dst = half ? (t ? an1 : an0) : (t ? ac1 : ac0);
                dst[i * 4 + h] = s;
            }
        }
        return;
    }
    if (b < P1_SPW0) { do_split(b - P1_SPX,  x,   xhi,   xlo,   NN * 256 / 4); return; }
    if (b < P1_SPW1) { do_split(b - P1_SPW0, Wm0, wmhi,  wmlo,  256 * 256 / 4); return; }
    if (b < P1_SPIH) { do_split(b - P1_SPW1, Wm1, wmhi + 256 * 256, wmlo + 256 * 256, 256 * 256 / 4); return; }
    if (b < P1_SPHH) { do_split(b - P1_SPIH, wih, wihhi, wihlo, 768 * 512 / 4); return; }
    if (b < P1_BM)   { do_split(b - P1_SPHH, whh, whhhi, whhlo, 768 * 256 / 4); return; }
    // ---- bmcat ----
    bm[tid] = bm0[tid];
    bm[tid + 256] = bm1[tid];
}

// ---------------- mma helper ----------------
__device__ __forceinline__ void mma16816(float* c, const unsigned* a, const unsigned* b) {
    asm volatile(
        "mma.sync.aligned.m16n8k16.row.col.f32.bf16.bf16.f32 "
        "{%0,%1,%2,%3},{%4,%5,%6,%7},{%8,%9},{%0,%1,%2,%3};"
        : "+f"(c[0]), "+f"(c[1]), "+f"(c[2]), "+f"(c[3])
        : "r"(a[0]), "r"(a[1]), "r"(a[2]), "r"(a[3]), "r"(b[0]), "r"(b[1]));
}

// ---------------- tensor-core GEMM body (cp.async double-buffered) ----------------
#define AST 40
#define ASZ (128 * AST)
#define BSZ (64 * AST)
#define GEMM_SMEM ((4 * ASZ + 4 * BSZ) * 2)

__device__ __forceinline__ void gemm_body(
    __nv_bfloat16* smem,
    const __nv_bfloat16* __restrict__ Ahi, const __nv_bfloat16* __restrict__ Alo,
    const __nv_bfloat16* __restrict__ Bhi, const __nv_bfloat16* __restrict__ Blo,
    const float* __restrict__ bias, float* __restrict__ C,
    int Nc, int K, int m0, int n0) {
    __nv_bfloat16* sA = smem;
    __nv_bfloat16* sB = smem + 4 * ASZ;

    int tid = threadIdx.x, lane = tid & 31, wid = tid >> 5;
    int wr = wid >> 1, wc = wid & 1;
    int g = lane >> 2, tq = lane & 3;

    float acc[2][4][4] = {};

    auto issue = [&](int kk, int st) {
        #pragma unroll
        for (int it = 0; it < 2; it++) {
            int ch = tid + it * 256;
            int r = ch >> 2, c = (ch & 3) * 8;
            unsigned dh = (unsigned)__cvta_generic_to_shared(&sA[(st * 2 + 0) * ASZ + r * AST + c]);
            unsigned dl = (unsigned)__cvta_generic_to_shared(&sA[(st * 2 + 1) * ASZ + r * AST + c]);
            asm volatile("cp.async.cg.shared.global [%0],[%1],16;" :: "r"(dh), "l"(&Ahi[(m0 + r) * K + kk + c]));
            asm volatile("cp.async.cg.shared.global [%0],[%1],16;" :: "r"(dl), "l"(&Alo[(m0 + r) * K + kk + c]));
        }
        {
            int r = tid >> 2, c = (tid & 3) * 8;
            unsigned dh = (unsigned)__cvta_generic_to_shared(&sB[(st * 2 + 0) * BSZ + r * AST + c]);
            unsigned dl = (unsigned)__cvta_generic_to_shared(&sB[(st * 2 + 1) * BSZ + r * AST + c]);
            asm volatile("cp.async.cg.shared.global [%0],[%1],16;" :: "r"(dh), "l"(&Bhi[(n0 + r) * K + kk + c]));
            asm volatile("cp.async.cg.shared.global [%0],[%1],16;" :: "r"(dl), "l"(&Blo[(n0 + r) * K + kk + c]));
        }
    };

    auto compute = [&](int st) {
        const __nv_bfloat16* Ah = sA + (st * 2 + 0) * ASZ;
        const __nv_bfloat16* Al = sA + (st * 2 + 1) * ASZ;
        const __nv_bfloat16* Bh = sB + (st * 2 + 0) * BSZ;
        const __nv_bfloat16* Bl = sB + (st * 2 + 1) * BSZ;
        #pragma unroll
        for (int k16 = 0; k16 < 32; k16 += 16) {
            unsigned ahi[2][4], alo[2][4], bhi[4][2], blo[4][2];
            #pragma unroll
            for (int mt = 0; mt < 2; mt++) {
                int ra = wr * 32 + mt * 16 + g;
                const __nv_bfloat16* p = &Ah[ra * AST + k16 + tq * 2];
                ahi[mt][0] = *(const unsigned*)p;
                ahi[mt][1] = *(const unsigned*)(p + 8 * AST);
                ahi[mt][2] = *(const unsigned*)(p + 8);
                ahi[mt][3] = *(const unsigned*)(p + 8 * AST + 8);
                const __nv_bfloat16* q = &Al[ra * AST + k16 + tq * 2];
                alo[mt][0] = *(const unsigned*)q;
                alo[mt][1] = *(const unsigned*)(q + 8 * AST);
                alo[mt][2] = *(const unsigned*)(q + 8);
                alo[mt][3] = *(const unsigned*)(q + 8 * AST + 8);
            }
            #pragma unroll
            for (int nt = 0; nt < 4; nt++) {
                int cb = wc * 32 + nt * 8 + g;
                const __nv_bfloat16* p = &Bh[cb * AST + k16 + tq * 2];
                bhi[nt][0] = *(const unsigned*)p;
                bhi[nt][1] = *(const unsigned*)(p + 8);
                const __nv_bfloat16* q = &Bl[cb * AST + k16 + tq * 2];
                blo[nt][0] = *(const unsigned*)q;
                blo[nt][1] = *(const unsigned*)(q + 8);
            }
            #pragma unroll
            for (int mt = 0; mt < 2; mt++)
                #pragma unroll
                for (int nt = 0; nt < 4; nt++) {
                    mma16816(acc[mt][nt], ahi[mt], bhi[nt]);
                    mma16816(acc[mt][nt], ahi[mt], blo[nt]);
                    mma16816(acc[mt][nt], alo[mt], bhi[nt]);
                }
        }
    };

    int nk = K / 32;
    issue(0, 0);
    asm volatile("cp.async.commit_group;");
    for (int kt = 0; kt < nk; kt++) {
        if (kt + 1 < nk) {
            issue((kt + 1) * 32, (kt + 1) & 1);
            asm volatile("cp.async.commit_group;");
            asm volatile("cp.async.wait_group 1;");
        } else {
            asm volatile("cp.async.wait_group 0;");
        }
        __syncthreads();
        compute(kt & 1);
        __syncthreads();
    }

    #pragma unroll
    for (int mt = 0; mt < 2; mt++) {
        int r0 = m0 + wr * 32 + mt * 16 + g;
        #pragma unroll
        for (int nt = 0; nt < 4; nt++) {
            int c0 = n0 + wc * 32 + nt * 8 + tq * 2;
            float2 b2 = *(const float2*)&bias[c0];
            float2 o0 = {acc[mt][nt][0] + b2.x, acc[mt][nt][1] + b2.y};
            float2 o1 = {acc[mt][nt][2] + b2.x, acc[mt][nt][3] + b2.y};
            *(float2*)&C[r0 * Nc + c0] = o0;
            *(float2*)&C[(r0 + 8) * Nc + c0] = o1;
        }
    }
}

__global__ void __launch_bounds__(256) gemm_bf16split(
    const __nv_bfloat16* __restrict__ Ahi, const __nv_bfloat16* __restrict__ Alo,
    const __nv_bfloat16* __restrict__ Bhi, const __nv_bfloat16* __restrict__ Blo,
    const float* __restrict__ bias, float* __restrict__ C, int Nc, int K) {
    extern __shared__ __nv_bfloat16 smem[];
    gemm_body(smem, Ahi, Alo, Bhi, Blo, bias, C, Nc, K, blockIdx.y * 128, blockIdx.x * 64);
}

// gi (z=0) and gh (z=1) fused in one launch
__global__ void __launch_bounds__(256) gemm_dual(
    const __nv_bfloat16* __restrict__ A0hi, const __nv_bfloat16* __restrict__ A0lo,
    const __nv_bfloat16* __restrict__ B0hi, const __nv_bfloat16* __restrict__ B0lo,
    const float* __restrict__ bias0, float* __restrict__ C0, int K0,
    const __nv_bfloat16* __restrict__ A1hi, const __nv_bfloat16* __restrict__ A1lo,
    const __nv_bfloat16* __restrict__ B1hi, const __nv_bfloat16* __restrict__ B1lo,
    const float* __restrict__ bias1, float* __restrict__ C1, int K1, int Nc) {
    extern __shared__ __nv_bfloat16 smem[];
    if (blockIdx.z == 0)
        gemm_body(smem, A0hi, A0lo, B0hi, B0lo, bias0, C0, Nc, K0, blockIdx.y * 128, blockIdx.x * 64);
    else
        gemm_body(smem, A1hi, A1lo, B1hi, B1lo, bias1, C1, Nc, K1, blockIdx.y * 128, blockIdx.x * 64);
}

// ---------------- sparse softmax attention + aggregate (writes bf16 hi/lo) ----------------
__global__ void attn_agg2(const float* __restrict__ eT0, const float* __restrict__ eT1,
                          const float* __restrict__ msgcat,
                          const float* __restrict__ ac0_, const float* __restrict__ an0_,
                          const float* __restrict__ ac1_, const float* __restrict__ an1_,
                          const float* __restrict__ ba0, const float* __restrict__ ba1,
                          __nv_bfloat16* __restrict__ ahi, __nv_bfloat16* __restrict__ alo) {
    __shared__ int   jl[512];
    __shared__ float wl[512];
    __shared__ float sv[512 * 4];
    __shared__ float red[256 * 4];
    __shared__ int   warp_off[8];
    __shared__ int   sbase;
    __shared__ float hmax[4], hsum[4];

    int t = blockIdx.y;
    const float* eT   = t ? eT1 : eT0;
    const float* acur = t ? ac1_ : ac0_;
    const float* anb  = t ? an1_ : an0_;
    const float* ba   = t ? ba1 : ba0;
    const float* msg  = msgcat + t * 256;

    int i = blockIdx.x;
    int tid = threadIdx.x;
    int lane = tid & 31, wid = tid >> 5;
    int oidx = i * 512 + t * 256 + tid;

    if (tid == 0) sbase = 0;
    for (int k = tid; k < 2048; k += 256) sv[k] = -INFINITY;
    __syncthreads();

    for (int q = 0; q < 8; q++) {
        int j = q * 256 + tid;
        float v = eT[i * NN + j];
        bool f = (v >= 0.f);
        unsigned m = __ballot_sync(0xffffffffu, f);
        int pre = __popc(m & ((1u << lane) - 1u));
        if (lane == 0) warp_off[wid] = __popc(m);
        __syncthreads();
        if (tid == 0) {
            int s = sbase;
            for (int w2 = 0; w2 < 8; w2++) { int c = warp_off[w2]; warp_off[w2] = s; s += c; }
            sbase = s;
        }
        __syncthreads();
        if (f) {
            int pos = warp_off[wid] + pre;
            if (pos < 512) { jl[pos] = j; wl[pos] = v; }
        }
        __syncthreads();
    }
    int E = sbase;
    if (E == 0) {
        ahi[oidx] = __float2bfloat16(0.f);
        alo[oidx] = __float2bfloat16(0.f);
        return;
    }
    if (E > 512) E = 512;

    float ac[4], bah[4];
    #pragma unroll
    for (int h = 0; h < 4; h++) { ac[h] = acur[i * 4 + h]; bah[h] = ba[h]; }

    for (int e = tid; e < E; e += 256) {
        int j = jl[e]; float w = wl[e];
        #pragma unroll
        for (int h = 0; h < 4; h++) {
            float v = anb[j * 4 + h] + ac[h] + bah[h];
            v = v > 0.f ? v : 0.2f * v;
            sv[e * 4 + h] = v * w;
        }
    }
    __syncthreads();

    #pragma unroll
    for (int h = 0; h < 4; h++) red[tid * 4 + h] = fmaxf(sv[tid * 4 + h], sv[(tid + 256) * 4 + h]);
    __syncthreads();
    for (int off = 128; off > 0; off >>= 1) {
        if (tid < off)
            #pragma unroll
            for (int h = 0; h < 4; h++) red[tid * 4 + h] = fmaxf(red[tid * 4 + h], red[(tid + off) * 4 + h]);
        __syncthreads();
    }
    if (tid < 4) hmax[tid] = red[tid];
    __syncthreads();

    for (int e = tid; e < 512; e += 256) {
        #pragma unroll
        for (int h = 0; h < 4; h++) sv[e * 4 + h] = expf(sv[e * 4 + h] - hmax[h]);
    }
    __syncthreads();

    #pragma unroll
    for (int h = 0; h < 4; h++) red[tid * 4 + h] = sv[tid * 4 + h] + sv[(tid + 256) * 4 + h];
    __syncthreads();
    for (int off = 128; off > 0; off >>= 1) {
        if (tid < off)
            #pragma unroll
            for (int h = 0; h < 4; h++) red[tid * 4 + h] += red[(tid + off) * 4 + h];
        __syncthreads();
    }
    if (tid < 4) hsum[tid] = red[tid];
    __syncthreads();

    for (int e = tid; e < E; e += 256) {
        #pragma unroll
        for (int h = 0; h < 4; h++) sv[e * 4 + h] *= (1.f / hsum[h]);
    }
    __syncthreads();

    int d = tid, h = d >> 6;
    float acc = 0.f;
    for (int e = 0; e < E; e++) acc += sv[e * 4 + h] * msg[jl[e] * 512 + d];

    __nv_bfloat16 hb = __float2bfloat16(acc);
    ahi[oidx] = hb;
    alo[oidx] = __float2bfloat16(acc - __bfloat162float(hb));
}

// ---------------- GRU gates + LayerNorm ----------------
__global__ void gru_ln(const float* __restrict__ gi_, const float* __restrict__ gh_,
                       const float* __restrict__ x, const float* __restrict__ g,
                       const float* __restrict__ b, float* __restrict__ out) {
    int i = blockIdx.x, d = threadIdx.x;
    const float* gi = gi_ + i * 768;
    const float* gh = gh_ + i * 768;
    float r = 1.f / (1.f + expf(-(gi[d] + gh[d])));
    float z = 1.f / (1.f + expf(-(gi[256 + d] + gh[256 + d])));
    float n = tanhf(gi[512 + d] + r * gh[512 + d]);
    float hv = (1.f - z) * n + z * x[i * 256 + d];

    __shared__ float ssum[8], ssq[8];
    __shared__ float mu_s, rs_s;
    float s = hv, q = hv * hv;
    #pragma unroll
    for (int off = 16; off > 0; off >>= 1) {
        s += __shfl_down_sync(0xffffffffu, s, off);
        q += __shfl_down_sync(0xffffffffu, q, off);
    }
    int lane = d & 31, wid = d >> 5;
    if (lane == 0) { ssum[wid] = s; ssq[wid] = q; }
    __syncthreads();
    if (d == 0) {
        float S = 0.f, Q = 0.f;
        for (int w2 = 0; w2 < 8; w2++) { S += ssum[w2]; Q += ssq[w2]; }
        float mu = S / 256.f;
        float var = Q / 256.f - mu * mu;
        mu_s = mu;
        rs_s = rsqrtf(var + 1e-5f);
    }
    __syncthreads();
    out[i * 256 + d] = (hv - mu_s) * rs_s * g[d] + b[d];
}

// ---------------- host orchestration (single stream, 5 launches) ----------------
extern "C" void kernel_launch(void* const* d_in, const int* in_sizes, int n_in,
                              void* d_out, int out_size) {
    const float* x    = (const float*)d_in[0];
    const float* adj0 = (const float*)d_in[1];
    const float* adj1 = (const float*)d_in[2];
    const float* w0   = (const float*)d_in[3];
    const float* w1   = (const float*)d_in[4];
    const float* Wm0  = (const float*)d_in[5];
    const float* bm0  = (const float*)d_in[6];
    const float* Wa0  = (const float*)d_in[7];
    const float* ba0  = (const float*)d_in[8];
    const float* Wm1  = (const float*)d_in[9];
    const float* bm1  = (const float*)d_in[10];
    const float* Wa1  = (const float*)d_in[11];
    const float* ba1  = (const float*)d_in[12];
    const float* wih  = (const float*)d_in[13];
    const float* whh  = (const float*)d_in[14];
    const float* bih  = (const float*)d_in[15];
    const float* bhh  = (const float*)d_in[16];
    const float* lng  = (const float*)d_in[17];
    const float* lnb  = (const float*)d_in[18];
    float* out = (float*)d_out;

    float *msg, *e0, *e1, *gi, *gh, *ac0, *an0, *ac1, *an1, *bm;
    cudaGetSymbolAddress((void**)&msg, g_msg);
    cudaGetSymbolAddress((void**)&e0,  g_e0);
    cudaGetSymbolAddress((void**)&e1,  g_e1);
    cudaGetSymbolAddress((void**)&gi,  g_gi);
    cudaGetSymbolAddress((void**)&gh,  g_gh);
    cudaGetSymbolAddress((void**)&ac0, g_ac0);
    cudaGetSymbolAddress((void**)&an0, g_an0);
    cudaGetSymbolAddress((void**)&ac1, g_ac1);
    cudaGetSymbolAddress((void**)&an1, g_an1);
    cudaGetSymbolAddress((void**)&bm,  g_bm);

    __nv_bfloat16 *xhi, *xlo, *ahi, *alo, *wmhi, *wmlo, *wihhi, *wihlo, *whhhi, *whhlo;
    cudaGetSymbolAddress((void**)&xhi,   g_xhi);
    cudaGetSymbolAddress((void**)&xlo,   g_xlo);
    cudaGetSymbolAddress((void**)&ahi,   g_ahi);
    cudaGetSymbolAddress((void**)&alo,   g_alo);
    cudaGetSymbolAddress((void**)&wmhi,  g_wmhi);
    cudaGetSymbolAddress((void**)&wmlo,  g_wmlo);
    cudaGetSymbolAddress((void**)&wihhi, g_wihhi);
    cudaGetSymbolAddress((void**)&wihlo, g_wihlo);
    cudaGetSymbolAddress((void**)&whhhi, g_whhhi);
    cudaGetSymbolAddress((void**)&whhlo, g_whhlo);

    cudaFuncSetAttribute(gemm_bf16split,
                         cudaFuncAttributeMaxDynamicSharedMemorySize, GEMM_SMEM);
    cudaFuncSetAttribute(gemm_dual,
                         cudaFuncAttributeMaxDynamicSharedMemorySize, GEMM_SMEM);

    // 1) transpose+mask, acoef, all bf16 splits, bias concat — one launch
    phase1<<<P1_GRID, 256>>>(x, adj0, w0, adj1, w1, Wa0, Wa1, Wm0, Wm1, wih, whh,
                             bm0, bm1, e0, e1, ac0, an0, ac1, an1,
                             xhi, xlo, wmhi, wmlo, wihhi, wihlo, whhhi, whhlo, bm);

    // 2) merged msg GEMM: [2048,512] = x @ [Wm0;Wm1]^T
    gemm_bf16split<<<dim3(8, 16), 256, GEMM_SMEM>>>(xhi, xlo, wmhi, wmlo, bm, msg, 512, 256);

    // 3) attention + aggregate (emits agg directly as bf16 hi/lo)
    attn_agg2<<<dim3(NN, 2), 256>>>(e0, e1, msg, ac0, an0, ac1, an1, ba0, ba1, ahi, alo);

    // 4) gi and gh GEMMs fused in one launch
    gemm_dual<<<dim3(12, 16, 2), 256, GEMM_SMEM>>>(
        ahi, alo, wihhi, wihlo, bih, gi, 512,
        xhi, xlo, whhhi, whhlo, bhh, gh, 256, 768);

    // 5) GRU gates + LayerNorm
    gru_ln<<<NN, 256>>>(gi, gh, x, lng, lnb, out);
}